// round 2
// baseline (speedup 1.0000x reference)
#include <cuda_runtime.h>

// Problem constants
#define K_DIM   256
#define NCODES  1024
#define NPIX    65536                 // 64 * 32 * 32 pixels
#define NQ      16777216ull           // 64 * 256 * 32 * 32 elements per (B,C,H,W) tensor

// Per-code squared norms ||w_j||^2, computed once per launch (graph-capturable).
__device__ float g_wsq[NCODES];

// ---------------------------------------------------------------------------
// Kernel 0: wsq[j] = sum_c w[j][c]^2  (sequential fp32 FMA chain per code)
// ---------------------------------------------------------------------------
__global__ void wsq_kernel(const float* __restrict__ w) {
    int code = blockIdx.x * blockDim.x + threadIdx.x;
    if (code < NCODES) {
        const float* row = w + code * K_DIM;
        float s = 0.0f;
        #pragma unroll 8
        for (int c = 0; c < K_DIM; c++) s = fmaf(row[c], row[c], s);
        g_wsq[code] = s;
    }
}

// ---------------------------------------------------------------------------
// Main kernel: per block of 64 pixels, compute distances to all 1024 codes,
// argmin with first-index tie-break, then gather codebook rows to output.
//
// Layout of x: (B, C, H, W) with B=64, C=256, H=W=32. Pixel p = b*1024 + s,
// flat[p][c] = x[b*C*1024 + c*1024 + s]. A block handles 64 consecutive p
// (never crossing an image boundary since 64 | 1024).
//
// Tiling: BM=64 pixels, BN=64 codes, BK=32, 256 threads, 4x4 microtile.
//   xsT[c][rp]  : full K-resident transposed x tile, 256x64 f32 (64 KB smem)
//   ws[k][col]  : 32x64 weight slice, padded stride 69 (conflict-free)
// ---------------------------------------------------------------------------
__global__ __launch_bounds__(256) void vq_kernel(
    const float* __restrict__ x,
    const float* __restrict__ w,
    float* __restrict__ out)
{
    extern __shared__ float sm[];
    float* xsT = sm;                 // [256][64]
    float* ws  = sm + K_DIM * 64;    // [32][69]
    __shared__ float s_xs[64];
    __shared__ int   s_idx[64];

    const int tid = threadIdx.x;
    const int p0  = blockIdx.x * 64;     // first pixel of this block
    const int b   = p0 >> 10;            // image index (1024 pixels / image)
    const int s0  = p0 & 1023;           // spatial offset within image
    const float* xb = x + (size_t)b * (K_DIM * 1024);

    // Load x tile transposed: xsT[c][rp] = x[b][c][s0+rp]  (coalesced per c-row)
    for (int t = tid; t < K_DIM * 64; t += 256) {
        int rp = t & 63, c = t >> 6;
        xsT[c * 64 + rp] = xb[(size_t)c * 1024 + s0 + rp];
    }
    __syncthreads();

    // ||x||^2 per pixel, sequential fp32 FMA chain over c (matches scalar order)
    if (tid < 64) {
        float s = 0.0f;
        #pragma unroll 8
        for (int c = 0; c < K_DIM; c++) {
            float v = xsT[c * 64 + tid];
            s = fmaf(v, v, s);
        }
        s_xs[tid] = s;
    }
    // (consumed only after later __syncthreads barriers)

    const int tx = tid & 15;   // code-tile column group (4 codes each)
    const int ty = tid >> 4;   // pixel row group (4 pixels each)

    float bestv[4];
    int   besti[4];
    #pragma unroll
    for (int i = 0; i < 4; i++) { bestv[i] = 3.402823466e38f; besti[i] = 0; }

    for (int n0 = 0; n0 < NCODES; n0 += 64) {
        float acc[4][4];
        #pragma unroll
        for (int i = 0; i < 4; i++)
            #pragma unroll
            for (int j = 0; j < 4; j++) acc[i][j] = 0.0f;

        for (int k0 = 0; k0 < K_DIM; k0 += 32) {
            __syncthreads();
            // Load weight slice: ws[k][col] = w[(n0+col)][k0+k]
            // lanes vary k fastest -> 128B coalesced global reads;
            // smem stride 69 (odd*? 69 = 5 mod 32, coprime) -> conflict-free STS.
            {
                int kk = tid & 31, colb = tid >> 5;
                #pragma unroll
                for (int cc = 0; cc < 8; cc++) {
                    int col = colb + cc * 8;
                    ws[kk * 69 + col] = w[(size_t)(n0 + col) * K_DIM + k0 + kk];
                }
            }
            __syncthreads();

            #pragma unroll
            for (int k = 0; k < 32; k++) {
                float4 av = *(const float4*)&xsT[(k0 + k) * 64 + ty * 4];
                float a0 = av.x, a1 = av.y, a2 = av.z, a3 = av.w;
                const float* wr = &ws[k * 69 + tx * 4];
                float b0 = wr[0], b1 = wr[1], b2 = wr[2], b3 = wr[3];
                acc[0][0] = fmaf(a0, b0, acc[0][0]);
                acc[0][1] = fmaf(a0, b1, acc[0][1]);
                acc[0][2] = fmaf(a0, b2, acc[0][2]);
                acc[0][3] = fmaf(a0, b3, acc[0][3]);
                acc[1][0] = fmaf(a1, b0, acc[1][0]);
                acc[1][1] = fmaf(a1, b1, acc[1][1]);
                acc[1][2] = fmaf(a1, b2, acc[1][2]);
                acc[1][3] = fmaf(a1, b3, acc[1][3]);
                acc[2][0] = fmaf(a2, b0, acc[2][0]);
                acc[2][1] = fmaf(a2, b1, acc[2][1]);
                acc[2][2] = fmaf(a2, b2, acc[2][2]);
                acc[2][3] = fmaf(a2, b3, acc[2][3]);
                acc[3][0] = fmaf(a3, b0, acc[3][0]);
                acc[3][1] = fmaf(a3, b1, acc[3][1]);
                acc[3][2] = fmaf(a3, b2, acc[3][2]);
                acc[3][3] = fmaf(a3, b3, acc[3][3]);
            }
        }

        // Score + running argmin. Replicate reference rounding:
        //   d2 = fl( fl(xs - fl(2*dot)) + wsq )   (no FMA contraction here)
        #pragma unroll
        for (int j = 0; j < 4; j++) {
            int code = n0 + tx * 4 + j;
            float wq = g_wsq[code];
            #pragma unroll
            for (int i = 0; i < 4; i++) {
                float t2 = __fadd_rn(s_xs[ty * 4 + i], -__fmul_rn(2.0f, acc[i][j]));
                float d2 = __fadd_rn(t2, wq);
                if (d2 < bestv[i]) { bestv[i] = d2; besti[i] = code; }  // strict < keeps first index
            }
        }
    }

    // Cross-thread reduction: 16 tx candidates per pixel row. Reuse xsT smem.
    __syncthreads();
    float* redv = sm;                       // [64][16]
    int*   redi = (int*)(sm + 64 * 16);     // [64][16]
    #pragma unroll
    for (int i = 0; i < 4; i++) {
        redv[(ty * 4 + i) * 16 + tx] = bestv[i];
        redi[(ty * 4 + i) * 16 + tx] = besti[i];
    }
    __syncthreads();
    if (tid < 64) {
        float bv = 3.402823466e38f;
        int   bi = 0x7fffffff;
        #pragma unroll
        for (int t = 0; t < 16; t++) {       // ascending tx == ascending code -> first-index tie-break
            float v = redv[tid * 16 + t];
            int  id = redi[tid * 16 + t];
            if (v < bv || (v == bv && id < bi)) { bv = v; bi = id; }
        }
        s_idx[tid] = bi;
    }
    __syncthreads();

    // Write idxs (as float, exactly representable) at offset 2*NQ
    if (tid < 64) out[2 * NQ + p0 + tid] = (float)s_idx[tid];

    // Gather codebook rows -> quantized and ste (identical values)
    const size_t obase = (size_t)b * (K_DIM * 1024) + s0;
    for (int t = tid; t < K_DIM * 64; t += 256) {
        int rp = t & 63, c = t >> 6;
        float v = w[(size_t)s_idx[rp] * K_DIM + c];
        size_t o = obase + (size_t)c * 1024 + rp;
        out[o]      = v;   // quantized
        out[NQ + o] = v;   // ste (numerically equal)
    }
}

// ---------------------------------------------------------------------------
extern "C" void kernel_launch(void* const* d_in, const int* in_sizes, int n_in,
                              void* d_out, int out_size) {
    const float* x = (const float*)d_in[0];
    const float* w = (const float*)d_in[1];
    // Robust input identification by element count (x = 16.7M, weight = 262144)
    if (n_in >= 2 && in_sizes[0] == NCODES * K_DIM) {
        w = (const float*)d_in[0];
        x = (const float*)d_in[1];
    }
    float* out = (float*)d_out;

    const size_t smem = (size_t)(K_DIM * 64 + 32 * 69) * sizeof(float);  // 74368 B
    cudaFuncSetAttribute(vq_kernel, cudaFuncAttributeMaxDynamicSharedMemorySize, (int)smem);

    wsq_kernel<<<NCODES / 256, 256>>>(w);
    vq_kernel<<<NPIX / 64, 256, smem>>>(x, w, out);
}

// round 3
// speedup vs baseline: 1.1602x; 1.1602x over previous
#include <cuda_runtime.h>

// Problem constants
#define K_DIM   256
#define NCODES  1024
#define NPIX    65536                 // 64 * 32 * 32 pixels
#define NQ      16777216ull           // elements per (B,C,H,W) tensor
#define BM      128                   // pixels per block
#define BN      128                   // codes per n-tile
#define BK      16                    // k-chunk

__device__ float g_wsq[NCODES];

// wsq[j] = sum_c w[j][c]^2 (sequential fp32 FMA chain)
__global__ void wsq_kernel(const float* __restrict__ w) {
    int code = blockIdx.x * blockDim.x + threadIdx.x;
    if (code < NCODES) {
        const float* row = w + code * K_DIM;
        float s = 0.0f;
        #pragma unroll 8
        for (int c = 0; c < K_DIM; c++) s = fmaf(row[c], row[c], s);
        g_wsq[code] = s;
    }
}

// ---- packed fp32 helpers (Blackwell f32x2 pipe; each lane is an exact fp32 FMA) ----
__device__ __forceinline__ unsigned long long dup2(float v) {
    unsigned long long r;
    asm("mov.b64 %0, {%1, %1};" : "=l"(r) : "f"(v));
    return r;
}
__device__ __forceinline__ void ffma2(unsigned long long& d, unsigned long long a, unsigned long long b) {
    asm("fma.rn.f32x2 %0, %1, %2, %0;" : "+l"(d) : "l"(a), "l"(b));
}
__device__ __forceinline__ void unpack2(float& lo, float& hi, unsigned long long v) {
    asm("mov.b64 {%0, %1}, %2;" : "=f"(lo), "=f"(hi) : "l"(v));
}

// ---------------------------------------------------------------------------
// Block = 128 pixels. Loop over 8 code tiles of 128. 256 threads, 8x8 micro,
// pixel-pairs packed in f32x2. x tile (full K) resident in smem transposed;
// w streamed double-buffered. Fused argmin + gather epilogue.
// ---------------------------------------------------------------------------
__global__ __launch_bounds__(256) void vq_kernel(
    const float* __restrict__ x,
    const float* __restrict__ w,
    float* __restrict__ out)
{
    extern __shared__ float sm[];
    float* xsT = sm;                      // [256][128]  (65536 floats)
    float* ws  = sm + K_DIM * BM;         // [2][BK][BN] (4096 floats)
    __shared__ float s_xs[BM];
    __shared__ float redv[BM][16];
    __shared__ int   redi[BM][16];
    __shared__ int   s_idx[BM];

    const int tid = threadIdx.x;
    const int p0  = blockIdx.x * BM;      // first pixel (128 | 1024, no image crossing)
    const int b   = p0 >> 10;
    const int s0  = p0 & 1023;
    const float* xb = x + (size_t)b * (K_DIM * 1024);

    // Load x tile transposed: xsT[c][rp] = x[b][c][s0+rp], vectorized float4
    for (int t = tid; t < K_DIM * BM / 4; t += 256) {
        int rq = t & 31, c = t >> 5;
        *(float4*)&xsT[c * BM + rq * 4] = *(const float4*)&xb[c * 1024 + s0 + rq * 4];
    }
    __syncthreads();

    // ||x||^2 per pixel (sequential fp32 FMA chain, matches R1)
    if (tid < BM) {
        float s = 0.0f;
        #pragma unroll 8
        for (int c = 0; c < K_DIM; c++) { float v = xsT[c * BM + tid]; s = fmaf(v, v, s); }
        s_xs[tid] = s;
    }
    __syncthreads();

    const int tx = tid & 15;    // code group: codes tx*8 .. tx*8+7 within tile
    const int ty = tid >> 4;    // pixel group: pixels ty*8 .. ty*8+7

    float bestv[8];
    int   besti[8];
    #pragma unroll
    for (int i = 0; i < 8; i++) { bestv[i] = 3.402823466e38f; besti[i] = 0; }

    // w streaming mapping: conflict-free STS (lanes = 32 consecutive codes)
    const int wcode = tid & 127;          // 0..127
    const int kq    = tid >> 7;           // 0..1 (which 8-k half of the chunk)

    for (int n0 = 0; n0 < NCODES; n0 += BN) {
        unsigned long long acc[4][8];     // [pixel-pair][code] f32x2 accumulators
        #pragma unroll
        for (int pp = 0; pp < 4; pp++)
            #pragma unroll
            for (int j = 0; j < 8; j++) acc[pp][j] = 0ull;

        const float* wg = w + (size_t)(n0 + wcode) * K_DIM;

        // preload chunk 0
        float4 pf0 = *(const float4*)&wg[kq * 8 + 0];
        float4 pf1 = *(const float4*)&wg[kq * 8 + 4];
        {
            float* buf = ws;
            int kb = kq * 8;
            buf[(kb + 0) * BN + wcode] = pf0.x; buf[(kb + 1) * BN + wcode] = pf0.y;
            buf[(kb + 2) * BN + wcode] = pf0.z; buf[(kb + 3) * BN + wcode] = pf0.w;
            buf[(kb + 4) * BN + wcode] = pf1.x; buf[(kb + 5) * BN + wcode] = pf1.y;
            buf[(kb + 6) * BN + wcode] = pf1.z; buf[(kb + 7) * BN + wcode] = pf1.w;
        }
        __syncthreads();

        for (int kc = 0; kc < K_DIM / BK; kc++) {
            const float* cur = ws + (kc & 1) * (BK * BN);
            float4 nf0, nf1;
            if (kc + 1 < K_DIM / BK) {         // prefetch next chunk (overlaps compute)
                nf0 = *(const float4*)&wg[(kc + 1) * BK + kq * 8 + 0];
                nf1 = *(const float4*)&wg[(kc + 1) * BK + kq * 8 + 4];
            }
            #pragma unroll
            for (int k = 0; k < BK; k++) {
                const ulonglong2* ar = (const ulonglong2*)&xsT[(kc * BK + k) * BM + ty * 8];
                ulonglong2 a01 = ar[0], a23 = ar[1];          // 4 pixel-pairs
                const float4* br = (const float4*)&cur[k * BN + tx * 8];
                float4 b03 = br[0], b47 = br[1];              // 8 codes
                unsigned long long bd;
                bd = dup2(b03.x);
                ffma2(acc[0][0], a01.x, bd); ffma2(acc[1][0], a01.y, bd);
                ffma2(acc[2][0], a23.x, bd); ffma2(acc[3][0], a23.y, bd);
                bd = dup2(b03.y);
                ffma2(acc[0][1], a01.x, bd); ffma2(acc[1][1], a01.y, bd);
                ffma2(acc[2][1], a23.x, bd); ffma2(acc[3][1], a23.y, bd);
                bd = dup2(b03.z);
                ffma2(acc[0][2], a01.x, bd); ffma2(acc[1][2], a01.y, bd);
                ffma2(acc[2][2], a23.x, bd); ffma2(acc[3][2], a23.y, bd);
                bd = dup2(b03.w);
                ffma2(acc[0][3], a01.x, bd); ffma2(acc[1][3], a01.y, bd);
                ffma2(acc[2][3], a23.x, bd); ffma2(acc[3][3], a23.y, bd);
                bd = dup2(b47.x);
                ffma2(acc[0][4], a01.x, bd); ffma2(acc[1][4], a01.y, bd);
                ffma2(acc[2][4], a23.x, bd); ffma2(acc[3][4], a23.y, bd);
                bd = dup2(b47.y);
                ffma2(acc[0][5], a01.x, bd); ffma2(acc[1][5], a01.y, bd);
                ffma2(acc[2][5], a23.x, bd); ffma2(acc[3][5], a23.y, bd);
                bd = dup2(b47.z);
                ffma2(acc[0][6], a01.x, bd); ffma2(acc[1][6], a01.y, bd);
                ffma2(acc[2][6], a23.x, bd); ffma2(acc[3][6], a23.y, bd);
                bd = dup2(b47.w);
                ffma2(acc[0][7], a01.x, bd); ffma2(acc[1][7], a01.y, bd);
                ffma2(acc[2][7], a23.x, bd); ffma2(acc[3][7], a23.y, bd);
            }
            if (kc + 1 < K_DIM / BK) {
                float* nxt = ws + ((kc + 1) & 1) * (BK * BN);
                int kb = kq * 8;
                nxt[(kb + 0) * BN + wcode] = nf0.x; nxt[(kb + 1) * BN + wcode] = nf0.y;
                nxt[(kb + 2) * BN + wcode] = nf0.z; nxt[(kb + 3) * BN + wcode] = nf0.w;
                nxt[(kb + 4) * BN + wcode] = nf1.x; nxt[(kb + 5) * BN + wcode] = nf1.y;
                nxt[(kb + 6) * BN + wcode] = nf1.z; nxt[(kb + 7) * BN + wcode] = nf1.w;
                __syncthreads();
            }
        }

        // Score + running argmin; reference rounding: d2 = fl(fl(xs - fl(2*dot)) + wsq)
        #pragma unroll
        for (int j = 0; j < 8; j++) {
            int codej = n0 + tx * 8 + j;
            float wq = g_wsq[codej];
            #pragma unroll
            for (int pp = 0; pp < 4; pp++) {
                float lo, hi;
                unpack2(lo, hi, acc[pp][j]);
                int i0 = pp * 2, i1 = pp * 2 + 1;
                float d0 = __fadd_rn(__fadd_rn(s_xs[ty * 8 + i0], -__fmul_rn(2.0f, lo)), wq);
                if (d0 < bestv[i0]) { bestv[i0] = d0; besti[i0] = codej; }
                float d1 = __fadd_rn(__fadd_rn(s_xs[ty * 8 + i1], -__fmul_rn(2.0f, hi)), wq);
                if (d1 < bestv[i1]) { bestv[i1] = d1; besti[i1] = codej; }
            }
        }
        // No sync needed here: next n-tile's preload STS targets ws[0], last read
        // at kc=14 which is fenced by the sync at end of kc=14; the post-preload
        // sync below orders it against stragglers in kc=15 compute.
    }

    // Cross-thread argmin reduction (16 tx candidates per pixel, ascending code)
    __syncthreads();
    #pragma unroll
    for (int i = 0; i < 8; i++) {
        redv[ty * 8 + i][tx] = bestv[i];
        redi[ty * 8 + i][tx] = besti[i];
    }
    __syncthreads();
    if (tid < BM) {
        float bv = 3.402823466e38f;
        int   bi = 0x7fffffff;
        #pragma unroll
        for (int t = 0; t < 16; t++) {
            float v = redv[tid][t];
            int  id = redi[tid][t];
            if (v < bv || (v == bv && id < bi)) { bv = v; bi = id; }
        }
        s_idx[tid] = bi;
    }
    __syncthreads();

    // idxs output (exactly representable as float)
    if (tid < BM) out[2 * NQ + p0 + tid] = (float)s_idx[tid];

    // Gather: quantized = w[idx], ste replicated as fl(fl(q - x) + x)
    const size_t obase = (size_t)b * (K_DIM * 1024) + s0;
    for (int t = tid; t < K_DIM * BM; t += 256) {
        int rp = t & 127, c = t >> 7;
        float q  = w[(size_t)s_idx[rp] * K_DIM + c];
        float xv = xb[c * 1024 + s0 + rp];
        size_t o = obase + (size_t)c * 1024 + rp;
        out[o]      = q;
        out[NQ + o] = __fadd_rn(__fsub_rn(q, xv), xv);
    }
}

// ---------------------------------------------------------------------------
extern "C" void kernel_launch(void* const* d_in, const int* in_sizes, int n_in,
                              void* d_out, int out_size) {
    const float* x = (const float*)d_in[0];
    const float* w = (const float*)d_in[1];
    if (n_in >= 2 && in_sizes[0] == NCODES * K_DIM) {  // robust input id by size
        w = (const float*)d_in[0];
        x = (const float*)d_in[1];
    }
    float* out = (float*)d_out;

    const size_t smem = (size_t)(K_DIM * BM + 2 * BK * BN) * sizeof(float);  // 147456 B
    static int attr_set = 0;
    cudaFuncSetAttribute(vq_kernel, cudaFuncAttributeMaxDynamicSharedMemorySize, (int)smem);
    (void)attr_set;

    wsq_kernel<<<NCODES / 256, 256>>>(w);
    vq_kernel<<<NPIX / BM, 256, smem>>>(x, w, out);
}

// round 4
// speedup vs baseline: 1.2003x; 1.0346x over previous
#include <cuda_runtime.h>

// Problem constants
#define K_DIM   256
#define NCODES  1024
#define NPIX    65536                 // 64 * 32 * 32 pixels
#define NQ      16777216ull           // elements per (B,C,H,W) tensor
#define BM      128                   // pixels per block
#define BN      128                   // codes per n-tile
#define BK      16                    // k-chunk
#define NTHR    512

__device__ float g_wsq[NCODES];

__global__ void wsq_kernel(const float* __restrict__ w) {
    int code = blockIdx.x * blockDim.x + threadIdx.x;
    if (code < NCODES) {
        const float* row = w + code * K_DIM;
        float s = 0.0f;
        #pragma unroll 8
        for (int c = 0; c < K_DIM; c++) s = fmaf(row[c], row[c], s);
        g_wsq[code] = s;
    }
}

// ---- packed fp32 helpers (each lane is an exact fp32 FMA; same k-order as R2) ----
__device__ __forceinline__ unsigned long long dup2(float v) {
    unsigned long long r;
    asm("mov.b64 %0, {%1, %1};" : "=l"(r) : "f"(v));
    return r;
}
__device__ __forceinline__ void ffma2(unsigned long long& d, unsigned long long a, unsigned long long b) {
    asm("fma.rn.f32x2 %0, %1, %2, %0;" : "+l"(d) : "l"(a), "l"(b));
}
__device__ __forceinline__ void unpack2(float& lo, float& hi, unsigned long long v) {
    asm("mov.b64 {%0, %1}, %2;" : "=f"(lo), "=f"(hi) : "l"(v));
}

// ---------------------------------------------------------------------------
// Block = 128 pixels, 512 threads (16 warps -> 4/SMSP for latency hiding).
// Microtile: 8 pixels (4 f32x2 pairs) x 4 codes -> 16 FFMA2 per k-step.
// x tile (full K=256) resident transposed in smem; w double-buffered.
// ---------------------------------------------------------------------------
__global__ __launch_bounds__(NTHR) void vq_kernel(
    const float* __restrict__ x,
    const float* __restrict__ w,
    float* __restrict__ out)
{
    extern __shared__ float sm[];
    float* xsT = sm;                      // [256][128]  (65536 floats, 128KB)
    float* ws  = sm + K_DIM * BM;         // [2][BK][BN] (4096 floats, 16KB)
    __shared__ float s_xs[BM];
    __shared__ int   s_idx[BM];

    const int tid = threadIdx.x;
    const int p0  = blockIdx.x * BM;
    const int b   = p0 >> 10;
    const int s0  = p0 & 1023;
    const float* xb = x + (size_t)b * (K_DIM * 1024);

    // Load x tile transposed (float4-vectorized, coalesced)
    for (int t = tid; t < K_DIM * BM / 4; t += NTHR) {
        int rq = t & 31, c = t >> 5;
        *(float4*)&xsT[c * BM + rq * 4] = *(const float4*)&xb[c * 1024 + s0 + rq * 4];
    }
    __syncthreads();

    // ||x||^2 per pixel (sequential fp32 FMA chain — reference order)
    if (tid < BM) {
        float s = 0.0f;
        #pragma unroll 8
        for (int c = 0; c < K_DIM; c++) { float v = xsT[c * BM + tid]; s = fmaf(v, v, s); }
        s_xs[tid] = s;
    }
    __syncthreads();

    const int tx = tid & 31;    // code group: 4 codes (tx*4 .. tx*4+3)
    const int ty = tid >> 5;    // pixel group: 8 pixels (ty*8 .. ty*8+7)

    float bestv[8];
    int   besti[8];
    #pragma unroll
    for (int i = 0; i < 8; i++) { bestv[i] = 3.402823466e38f; besti[i] = 0; }

    // w streaming: each thread owns (code = tid&127, k-quarter = tid>>7)
    const int wcode = tid & 127;
    const int kq    = tid >> 7;           // 0..3
    const float* wgp = w + (size_t)wcode * K_DIM + kq * 4;

    for (int n0 = 0; n0 < NCODES; n0 += BN) {
        unsigned long long acc[4][4];     // [pixel-pair][code]
        #pragma unroll
        for (int pp = 0; pp < 4; pp++)
            #pragma unroll
            for (int j = 0; j < 4; j++) acc[pp][j] = 0ull;

        const float* wg = wgp + (size_t)n0 * K_DIM;

        // preload chunk 0
        {
            float4 f = *(const float4*)&wg[0];
            int kb = kq * 4;
            ws[(kb + 0) * BN + wcode] = f.x; ws[(kb + 1) * BN + wcode] = f.y;
            ws[(kb + 2) * BN + wcode] = f.z; ws[(kb + 3) * BN + wcode] = f.w;
        }
        __syncthreads();

        for (int kc = 0; kc < K_DIM / BK; kc++) {
            const float* cur = ws + (kc & 1) * (BK * BN);
            float4 nf;
            if (kc + 1 < K_DIM / BK)
                nf = *(const float4*)&wg[(kc + 1) * BK];
            #pragma unroll
            for (int k = 0; k < BK; k++) {
                const ulonglong2* ar = (const ulonglong2*)&xsT[(kc * BK + k) * BM + ty * 8];
                ulonglong2 a01 = ar[0], a23 = ar[1];          // 4 pixel-pairs (broadcast LDS)
                float4 b4 = *(const float4*)&cur[k * BN + tx * 4];
                unsigned long long bd;
                bd = dup2(b4.x);
                ffma2(acc[0][0], a01.x, bd); ffma2(acc[1][0], a01.y, bd);
                ffma2(acc[2][0], a23.x, bd); ffma2(acc[3][0], a23.y, bd);
                bd = dup2(b4.y);
                ffma2(acc[0][1], a01.x, bd); ffma2(acc[1][1], a01.y, bd);
                ffma2(acc[2][1], a23.x, bd); ffma2(acc[3][1], a23.y, bd);
                bd = dup2(b4.z);
                ffma2(acc[0][2], a01.x, bd); ffma2(acc[1][2], a01.y, bd);
                ffma2(acc[2][2], a23.x, bd); ffma2(acc[3][2], a23.y, bd);
                bd = dup2(b4.w);
                ffma2(acc[0][3], a01.x, bd); ffma2(acc[1][3], a01.y, bd);
                ffma2(acc[2][3], a23.x, bd); ffma2(acc[3][3], a23.y, bd);
            }
            if (kc + 1 < K_DIM / BK) {
                float* nxt = ws + ((kc + 1) & 1) * (BK * BN);
                int kb = kq * 4;
                nxt[(kb + 0) * BN + wcode] = nf.x; nxt[(kb + 1) * BN + wcode] = nf.y;
                nxt[(kb + 2) * BN + wcode] = nf.z; nxt[(kb + 3) * BN + wcode] = nf.w;
                __syncthreads();
            }
        }

        // Score + running argmin; reference rounding: d2 = fl(fl(xs - fl(2*dot)) + wsq)
        #pragma unroll
        for (int j = 0; j < 4; j++) {
            int codej = n0 + tx * 4 + j;
            float wq = g_wsq[codej];
            #pragma unroll
            for (int pp = 0; pp < 4; pp++) {
                float lo, hi;
                unpack2(lo, hi, acc[pp][j]);
                int i0 = pp * 2, i1 = pp * 2 + 1;
                float d0 = __fadd_rn(__fadd_rn(s_xs[ty * 8 + i0], -__fmul_rn(2.0f, lo)), wq);
                if (d0 < bestv[i0]) { bestv[i0] = d0; besti[i0] = codej; }
                float d1 = __fadd_rn(__fadd_rn(s_xs[ty * 8 + i1], -__fmul_rn(2.0f, hi)), wq);
                if (d1 < bestv[i1]) { bestv[i1] = d1; besti[i1] = codej; }
            }
        }
        // buf0 last read at kc=14, fenced by the sync inside kc=14; next-tile
        // preload writes buf0 only after all threads passed that barrier.
    }

    // Cross-thread argmin reduction: 32 tx candidates per pixel.
    // Overlay reduction arrays on the (now dead) xsT smem region.
    __syncthreads();
    float* redv = sm;                        // [128][32]
    int*   redi = (int*)(sm + BM * 32);      // [128][32]
    #pragma unroll
    for (int i = 0; i < 8; i++) {
        redv[(ty * 8 + i) * 32 + tx] = bestv[i];
        redi[(ty * 8 + i) * 32 + tx] = besti[i];
    }
    __syncthreads();
    if (tid < BM) {
        float bv = 3.402823466e38f;
        int   bi = 0x7fffffff;
        #pragma unroll
        for (int t = 0; t < 32; t++) {       // ascending tx == ascending code
            float v = redv[tid * 32 + t];
            int  id = redi[tid * 32 + t];
            if (v < bv || (v == bv && id < bi)) { bv = v; bi = id; }
        }
        s_idx[tid] = bi;
    }
    __syncthreads();

    // idxs output (exactly representable as float)
    if (tid < BM) out[2 * NQ + p0 + tid] = (float)s_idx[tid];

    // Gather: quantized = w[idx], ste = fl(fl(q - x) + x) (reference rounding)
    const size_t obase = (size_t)b * (K_DIM * 1024) + s0;
    for (int t = tid; t < K_DIM * BM; t += NTHR) {
        int rp = t & 127, c = t >> 7;
        float q  = w[(size_t)s_idx[rp] * K_DIM + c];
        float xv = xb[c * 1024 + s0 + rp];
        size_t o = obase + (size_t)c * 1024 + rp;
        out[o]      = q;
        out[NQ + o] = __fadd_rn(__fsub_rn(q, xv), xv);
    }
}

// ---------------------------------------------------------------------------
extern "C" void kernel_launch(void* const* d_in, const int* in_sizes, int n_in,
                              void* d_out, int out_size) {
    const float* x = (const float*)d_in[0];
    const float* w = (const float*)d_in[1];
    if (n_in >= 2 && in_sizes[0] == NCODES * K_DIM) {  // robust input id by size
        w = (const float*)d_in[0];
        x = (const float*)d_in[1];
    }
    float* out = (float*)d_out;

    const size_t smem = (size_t)(K_DIM * BM + 2 * BK * BN) * sizeof(float);  // 147456 B
    cudaFuncSetAttribute(vq_kernel, cudaFuncAttributeMaxDynamicSharedMemorySize, (int)smem);

    wsq_kernel<<<NCODES / 256, 256>>>(w);
    vq_kernel<<<NPIX / BM, NTHR, smem>>>(x, w, out);
}

// round 8
// speedup vs baseline: 1.3083x; 1.0899x over previous
#include <cuda_runtime.h>
#include <cuda_bf16.h>
#include <cstdint>

#define K_DIM   256
#define NCODES  1024
#define NPIX    65536
#define NQ      16777216ull
#define BM      128           // pixels per CTA
#define BN      128           // codes per n-iter
#define NTHR    512
#define APAD    136           // pitch (b32 words): bank = (8*k2 + col) % 32, conflict-free
#define BK2     32            // k2-rows per B tile (=64 k)
#define NTILES  12            // 3 products x 4 tiles
#define MARGIN  4e-4f         // rescue window (~13 ulp at scale 256); >> 2*Delta = 1.3e-4
#define FLTMAX  3.402823466e38f

__device__ float g_wsq[NCODES];
// Pair-packed bf16 codebook, [k2][code]: rows 0..127 = hi pairs, 128..255 = lo pairs
__device__ uint32_t g_wp[256 * NCODES];

static __device__ __forceinline__ uint32_t pack_bf2(__nv_bfloat16 a, __nv_bfloat16 b) {
    return (uint32_t)__bfloat16_as_ushort(a) | ((uint32_t)__bfloat16_as_ushort(b) << 16);
}

__device__ __forceinline__ void mma16816(float* c, uint32_t a0, uint32_t a1, uint32_t a2, uint32_t a3,
                                         uint32_t b0, uint32_t b1) {
    asm volatile("mma.sync.aligned.m16n8k16.row.col.f32.bf16.bf16.f32 "
                 "{%0,%1,%2,%3}, {%4,%5,%6,%7}, {%8,%9}, {%0,%1,%2,%3};"
                 : "+f"(c[0]), "+f"(c[1]), "+f"(c[2]), "+f"(c[3])
                 : "r"(a0), "r"(a1), "r"(a2), "r"(a3), "r"(b0), "r"(b1));
}

// ---------------- prep kernels ----------------
__global__ void wsq_kernel(const float* __restrict__ w) {
    int code = blockIdx.x * blockDim.x + threadIdx.x;
    if (code < NCODES) {
        const float* row = w + code * K_DIM;
        float s = 0.0f;
        #pragma unroll 8
        for (int c = 0; c < K_DIM; c++) s = fmaf(row[c], row[c], s);
        g_wsq[code] = s;
    }
}
__global__ void wpack_kernel(const float* __restrict__ w) {
    int t = blockIdx.x * blockDim.x + threadIdx.x;
    int code = t & (NCODES - 1), k2 = t >> 10;
    float2 v = *(const float2*)&w[code * K_DIM + k2 * 2];
    __nv_bfloat16 h0 = __float2bfloat16(v.x), h1 = __float2bfloat16(v.y);
    __nv_bfloat16 l0 = __float2bfloat16(v.x - __bfloat162float(h0));
    __nv_bfloat16 l1 = __float2bfloat16(v.y - __bfloat162float(h1));
    g_wp[k2 * NCODES + code]         = pack_bf2(h0, h1);
    g_wp[(128 + k2) * NCODES + code] = pack_bf2(l0, l1);
}

__device__ __forceinline__ int srcrow(int tl) {   // B source k2-row: tiles 0-3 hi, 4-7 lo, 8-11 hi
    return (tl < 4) ? tl * 32 : (tl < 8) ? 128 + (tl - 4) * 32 : (tl - 8) * 32;
}

// ---------------- main kernel ----------------
__global__ __launch_bounds__(NTHR) void vq_kernel(
    const float* __restrict__ x,
    const float* __restrict__ w,
    float* __restrict__ out)
{
    extern __shared__ __align__(16) uint32_t smw[];
    uint32_t* Ap  = smw;                   // [256][APAD] pair-packed x (hi 0..127, lo 128..255)
    uint32_t* Bsm = smw + 256 * APAD;      // [2][BK2][APAD]; staging overlay in prologue
    __shared__ float s_wsq[NCODES];
    __shared__ float s_xs[BM];
    __shared__ int   s_idx[BM];
    __shared__ float s_xrow[K_DIM];
    __shared__ int   s_cand[BM][8];
    __shared__ int   s_ccnt[BM];
    __shared__ int   s_flag[BM];
    __shared__ int   s_nflag;

    const int tid  = threadIdx.x;
    const int wid  = tid >> 5, lane = tid & 31;
    const int g    = lane >> 2, tig = lane & 3;
    const int wm   = wid >> 2, wn = wid & 3;
    const int p0   = blockIdx.x * BM;
    const int b    = p0 >> 10;
    const int s0   = p0 & 1023;
    const float* xb = x + (size_t)b * (K_DIM * 1024);

    for (int t = tid; t < NCODES; t += NTHR) s_wsq[t] = g_wsq[t];

    // ---- stage x -> exact ||x||^2 + pair-packed bf16 hi/lo in Ap ----
    {
        float* stg = (float*)Bsm;
        float xacc = 0.0f;
        const int cpx = tid & 127, cq = tid >> 7;
        for (int c = 0; c < 4; c++) {
            __syncthreads();
            for (int t = tid; t < 64 * 32; t += NTHR) {
                int rq = t & 31, k = t >> 5;
                *(float4*)&stg[k * BM + rq * 4] =
                    *(const float4*)&xb[(size_t)(c * 64 + k) * 1024 + s0 + rq * 4];
            }
            __syncthreads();
            if (tid < BM) {
                #pragma unroll 8
                for (int k = 0; k < 64; k++) { float v = stg[k * BM + tid]; xacc = fmaf(v, v, xacc); }
            }
            #pragma unroll
            for (int j = 0; j < 8; j++) {
                int k2l = cq * 8 + j;
                float v0 = stg[(k2l * 2) * BM + cpx];
                float v1 = stg[(k2l * 2 + 1) * BM + cpx];
                __nv_bfloat16 h0 = __float2bfloat16(v0), h1 = __float2bfloat16(v1);
                __nv_bfloat16 l0 = __float2bfloat16(v0 - __bfloat162float(h0));
                __nv_bfloat16 l1 = __float2bfloat16(v1 - __bfloat162float(h1));
                Ap[(c * 32 + k2l) * APAD + cpx]       = pack_bf2(h0, h1);
                Ap[(128 + c * 32 + k2l) * APAD + cpx] = pack_bf2(l0, l1);
            }
        }
        __syncthreads();
        if (tid < BM) s_xs[tid] = xacc;
        __syncthreads();
    }

    // ---- HMMA mainloop: 8 n-iters x 12 tiles x 4 k16-steps, warp tile 32x32 ----
    const int lrow = tid >> 4, lci = tid & 15;
    // per e-slot top-3 values / top-2 indices
    float tv1[4], tv2[4], tv3[4];
    int   ti1[4], ti2[4];
    #pragma unroll
    for (int e = 0; e < 4; e++) { tv1[e] = tv2[e] = tv3[e] = FLTMAX; ti1[e] = ti2[e] = 0x7fffffff; }

    for (int n0 = 0; n0 < NCODES; n0 += BN) {
        float acc[2][4][4];
        #pragma unroll
        for (int mb = 0; mb < 2; mb++)
            #pragma unroll
            for (int nb = 0; nb < 4; nb++)
                #pragma unroll
                for (int e = 0; e < 4; e++) acc[mb][nb][e] = 0.0f;

        int4 pr0, pr1;
        {
            const int4* src = (const int4*)(g_wp + (size_t)(srcrow(0) + lrow) * NCODES + n0);
            pr0 = src[lci]; pr1 = src[lci + 16];
        }
        *(int4*)&Bsm[lrow * APAD + 4 * lci]      = pr0;
        *(int4*)&Bsm[lrow * APAD + 4 * lci + 64] = pr1;

        for (int tl = 0; tl < NTILES; tl++) {
            if (tl + 1 < NTILES) {
                const int4* src = (const int4*)(g_wp + (size_t)(srcrow(tl + 1) + lrow) * NCODES + n0);
                pr0 = src[lci]; pr1 = src[lci + 16];
            }
            __syncthreads();
            const uint32_t* Bt = Bsm + (tl & 1) * (BK2 * APAD);
            #pragma unroll
            for (int ws = 0; ws < 4; ws++) {
                const int v = tl * 4 + ws;
                const int abase = ((v >= 32) ? 128 : 0) + (v & 15) * 8;
                uint32_t b0[4], b1[4];
                #pragma unroll
                for (int nb = 0; nb < 4; nb++) {
                    int ncol = wn * 32 + nb * 8 + g;
                    b0[nb] = Bt[(ws * 8 + tig) * APAD + ncol];
                    b1[nb] = Bt[(ws * 8 + tig + 4) * APAD + ncol];
                }
                #pragma unroll
                for (int mb = 0; mb < 2; mb++) {
                    int m0 = wm * 32 + mb * 16;
                    uint32_t a0 = Ap[(abase + tig) * APAD + m0 + g];
                    uint32_t a1 = Ap[(abase + tig) * APAD + m0 + g + 8];
                    uint32_t a2 = Ap[(abase + tig + 4) * APAD + m0 + g];
                    uint32_t a3 = Ap[(abase + tig + 4) * APAD + m0 + g + 8];
                    #pragma unroll
                    for (int nb = 0; nb < 4; nb++)
                        mma16816(acc[mb][nb], a0, a1, a2, a3, b0[nb], b1[nb]);
                }
            }
            if (tl + 1 < NTILES) {
                uint32_t* nbuf = Bsm + ((tl + 1) & 1) * (BK2 * APAD);
                *(int4*)&nbuf[lrow * APAD + 4 * lci]      = pr0;
                *(int4*)&nbuf[lrow * APAD + 4 * lci + 64] = pr1;
            }
        }

        // ---- scoring epilogue with top-3 tracking (ascending code order per slot) ----
        #pragma unroll
        for (int nb = 0; nb < 4; nb++) {
            const int code0 = n0 + wn * 32 + nb * 8 + 2 * tig;
            const float wq0 = s_wsq[code0], wq1 = s_wsq[code0 + 1];
            #pragma unroll
            for (int mb = 0; mb < 2; mb++) {
                const float xs0 = s_xs[wm * 32 + mb * 16 + g];
                const float xs1 = s_xs[wm * 32 + mb * 16 + g + 8];
                #pragma unroll
                for (int q = 0; q < 4; q++) {
                    const float xsv  = (q < 2) ? xs0 : xs1;
                    const float wqv  = (q & 1) ? wq1 : wq0;
                    const int   cd   = code0 + (q & 1);
                    const int   e    = mb * 2 + (q >> 1);
                    float d = __fadd_rn(__fadd_rn(xsv, -__fmul_rn(2.0f, acc[mb][nb][q])), wqv);
                    if (d < tv1[e]) { tv3[e] = tv2[e]; tv2[e] = tv1[e]; ti2[e] = ti1[e]; tv1[e] = d; ti1[e] = cd; }
                    else if (d < tv2[e]) { tv3[e] = tv2[e]; tv2[e] = d; ti2[e] = cd; }
                    else if (d < tv3[e]) { tv3[e] = d; }
                }
            }
        }
    }

    // ---- dump slots, compute exact global top-2, collect rescue candidates ----
    __syncthreads();                           // Ap region now dead -> overlay
    float* sv1 = (float*)smw;                  // [128][16]
    int*   si1 = (int*)(smw + 2048);
    float* sv2 = (float*)(smw + 4096);
    int*   si2 = (int*)(smw + 6144);
    float* sv3 = (float*)(smw + 8192);
    float* rv  = (float*)(smw + 10240);        // rescue scratch [512]
    int*   ri  = (int*)(smw + 10752);
    #pragma unroll
    for (int e = 0; e < 4; e++) {
        int px = wm * 32 + (e >> 1) * 16 + g + 8 * (e & 1);
        int sl = wn * 4 + tig;
        sv1[px * 16 + sl] = tv1[e]; si1[px * 16 + sl] = ti1[e];
        sv2[px * 16 + sl] = tv2[e]; si2[px * 16 + sl] = ti2[e];
        sv3[px * 16 + sl] = tv3[e];
    }
    if (tid == 0) s_nflag = 0;
    __syncthreads();

    if (tid < BM) {
        float m1 = FLTMAX; int mi1 = 0x7fffffff;
        #pragma unroll
        for (int s = 0; s < 16; s++) {
            float v = sv1[tid * 16 + s]; int i = si1[tid * 16 + s];
            if (v < m1 || (v == m1 && i < mi1)) { m1 = v; mi1 = i; }
        }
        const float lim = m1 + MARGIN;
        int cnt = 1; bool full = false;
        s_cand[tid][0] = mi1;
        #pragma unroll
        for (int s = 0; s < 16; s++) {
            float v1 = sv1[tid * 16 + s], v2 = sv2[tid * 16 + s], v3 = sv3[tid * 16 + s];
            int   i1 = si1[tid * 16 + s], i2 = si2[tid * 16 + s];
            if (v1 <= lim && i1 != mi1) { if (cnt < 8) s_cand[tid][cnt] = i1; cnt++; }
            if (v2 <= lim && i2 != mi1) { if (cnt < 8) s_cand[tid][cnt] = i2; cnt++; }
            if (v3 <= lim) full = true;
        }
        if (cnt > 8) full = true;
        s_ccnt[tid] = full ? 255 : cnt;
        s_idx[tid] = mi1;
        if (full || cnt > 1) { int sl = atomicAdd(&s_nflag, 1); s_flag[sl] = tid; }
    }
    __syncthreads();

    // ---- rescue: exact sequential-fmaf rescoring (matches reference bit-behavior) ----
    const int nflag = s_nflag;
    for (int f = 0; f < nflag; f++) {
        const int px = s_flag[f];
        if (tid < 256) s_xrow[tid] = xb[(size_t)tid * 1024 + s0 + px];
        __syncthreads();
        const int cnt = s_ccnt[px];
        if (cnt != 255) {
            if (tid < cnt) {
                int code = s_cand[px][tid];
                const float* wr = w + (size_t)code * K_DIM;
                float dot = 0.0f;
                #pragma unroll 8
                for (int k = 0; k < K_DIM; k++) dot = fmaf(s_xrow[k], wr[k], dot);
                rv[tid] = __fadd_rn(__fadd_rn(s_xs[px], -__fmul_rn(2.0f, dot)), s_wsq[code]);
                ri[tid] = code;
            }
            __syncthreads();
            if (tid == 0) {
                float bv = FLTMAX; int bi = 0x7fffffff;
                for (int t = 0; t < cnt; t++) {
                    float v = rv[t]; int id = ri[t];
                    if (v < bv || (v == bv && id < bi)) { bv = v; bi = id; }
                }
                s_idx[px] = bi;
            }
        } else {
            // full exact rescore over all 1024 codes (rare safety net)
            float bv = FLTMAX; int bi = 0x7fffffff;
            #pragma unroll
            for (int j = 0; j < 2; j++) {
                int code = tid * 2 + j;
                const float* wr = w + (size_t)code * K_DIM;
                float dot = 0.0f;
                for (int k = 0; k < K_DIM; k++) dot = fmaf(s_xrow[k], wr[k], dot);
                float d2 = __fadd_rn(__fadd_rn(s_xs[px], -__fmul_rn(2.0f, dot)), s_wsq[code]);
                if (d2 < bv || (d2 == bv && code < bi)) { bv = d2; bi = code; }
            }
            rv[tid] = bv; ri[tid] = bi;
            __syncthreads();
            if (tid == 0) {
                float bvv = FLTMAX; int bii = 0x7fffffff;
                for (int t = 0; t < NTHR; t++) {
                    float v = rv[t]; int id = ri[t];
                    if (v < bvv || (v == bvv && id < bii)) { bvv = v; bii = id; }
                }
                s_idx[px] = bii;
            }
        }
        __syncthreads();
    }

    // ---- outputs ----
    if (tid < BM) out[2 * NQ + p0 + tid] = (float)s_idx[tid];

    const size_t obase = (size_t)b * (K_DIM * 1024) + s0;
    for (int t = tid; t < K_DIM * BM; t += NTHR) {
        int rp = t & 127, c = t >> 7;
        float q  = w[(size_t)s_idx[rp] * K_DIM + c];
        float xv = xb[(size_t)c * 1024 + s0 + rp];
        size_t o = obase + (size_t)c * 1024 + rp;
        out[o]      = q;
        out[NQ + o] = __fadd_rn(__fsub_rn(q, xv), xv);
    }
}

// ---------------------------------------------------------------------------
extern "C" void kernel_launch(void* const* d_in, const int* in_sizes, int n_in,
                              void* d_out, int out_size) {
    const float* x = (const float*)d_in[0];
    const float* w = (const float*)d_in[1];
    if (n_in >= 2 && in_sizes[0] == NCODES * K_DIM) {
        w = (const float*)d_in[0];
        x = (const float*)d_in[1];
    }
    float* out = (float*)d_out;

    const size_t smem = (size_t)(256 * APAD + 2 * BK2 * APAD) * sizeof(uint32_t);  // 174080 B
    cudaFuncSetAttribute(vq_kernel, cudaFuncAttributeMaxDynamicSharedMemorySize, (int)smem);

    wsq_kernel<<<NCODES / 256, 256>>>(w);
    wpack_kernel<<<(NCODES * 128) / 256, 256>>>(w);
    vq_kernel<<<NPIX / BM, NTHR, smem>>>(x, w, out);
}

// round 9
// speedup vs baseline: 1.4148x; 1.0814x over previous
#include <cuda_runtime.h>
#include <cuda_fp16.h>
#include <cstdint>

#define K_DIM   256
#define NCODES  1024
#define NPIX    65536
#define NQ      16777216ull
#define BM      128           // pixels per CTA
#define BN      128           // codes per n-iter
#define NTHR    512
#define APAD    136           // pitch (b32 words): bank = (8*k2 + col) % 32, conflict-free
#define MARGIN  8e-4f         // > 2 * deterministic d2 error bound (2.9e-4) for fp16 product
#define FLTMAX  3.402823466e38f

__device__ float g_wsq[NCODES];
// Pair-packed fp16 codebook, [k2][code] layout (k2 = 0..127)
__device__ uint32_t g_wp[128 * NCODES];

static __device__ __forceinline__ uint32_t pack_h2(float a, float b) {
    __half2 h = __floats2half2_rn(a, b);
    return *(uint32_t*)&h;
}

__device__ __forceinline__ void mma16816(float* c, uint32_t a0, uint32_t a1, uint32_t a2, uint32_t a3,
                                         uint32_t b0, uint32_t b1) {
    asm volatile("mma.sync.aligned.m16n8k16.row.col.f32.f16.f16.f32 "
                 "{%0,%1,%2,%3}, {%4,%5,%6,%7}, {%8,%9}, {%0,%1,%2,%3};"
                 : "+f"(c[0]), "+f"(c[1]), "+f"(c[2]), "+f"(c[3])
                 : "r"(a0), "r"(a1), "r"(a2), "r"(a3), "r"(b0), "r"(b1));
}

// ---------------- prep kernels ----------------
// wsq: 32 codes per block, coalesced smem staging, then exact sequential fmaf
// (identical accumulation order/values to all prior passing rounds).
__global__ void wsq_kernel(const float* __restrict__ w) {
    __shared__ float s[32 * K_DIM];
    const int blk = blockIdx.x, tid = threadIdx.x;
    const float* src = w + (size_t)blk * 32 * K_DIM;
    for (int i = tid; i < 32 * K_DIM / 4; i += 256)
        *(float4*)&s[i * 4] = *(const float4*)&src[i * 4];
    __syncthreads();
    if (tid < 32) {
        float acc = 0.0f;
        #pragma unroll 8
        for (int c = 0; c < K_DIM; c++) { float v = s[tid * K_DIM + c]; acc = fmaf(v, v, acc); }
        g_wsq[blk * 32 + tid] = acc;
    }
}
// wpack: coalesced reads (lanes sweep k2 within one code row)
__global__ void wpack_kernel(const float* __restrict__ w) {
    int t = blockIdx.x * blockDim.x + threadIdx.x;   // 131072
    int k2 = t & 127, code = t >> 7;
    float2 v = *(const float2*)&w[code * K_DIM + k2 * 2];
    g_wp[k2 * NCODES + code] = pack_h2(v.x, v.y);
}

// ---------------- main kernel ----------------
__global__ __launch_bounds__(NTHR) void vq_kernel(
    const float* __restrict__ x,
    const float* __restrict__ w,
    float* __restrict__ out)
{
    extern __shared__ __align__(16) uint32_t smw[];
    uint32_t* Ap  = smw;                   // [128][APAD] fp16-pair-packed x
    uint32_t* Bsm = smw + 128 * APAD;      // [128][APAD] fp16-pair-packed codes; staging overlay
    __shared__ float s_wsq[NCODES];
    __shared__ float s_xs[BM];
    __shared__ int   s_idx[BM];
    __shared__ float s_xrow[K_DIM];
    __shared__ int   s_cand[BM][8];
    __shared__ int   s_ccnt[BM];
    __shared__ int   s_flag[BM];
    __shared__ int   s_nflag;

    const int tid  = threadIdx.x;
    const int wid  = tid >> 5, lane = tid & 31;
    const int g    = lane >> 2, tig = lane & 3;
    const int wm   = wid >> 2, wn = wid & 3;
    const int p0   = blockIdx.x * BM;
    const int b    = p0 >> 10;
    const int s0   = p0 & 1023;
    const float* xb = x + (size_t)b * (K_DIM * 1024);

    for (int t = tid; t < NCODES; t += NTHR) s_wsq[t] = g_wsq[t];

    // ---- stage x -> exact ||x||^2 + fp16-pair-packed Ap ----
    {
        float* stg = (float*)Bsm;          // [64 k][128 px] f32 chunk (32KB)
        float xacc = 0.0f;
        const int cpx = tid & 127, cq = tid >> 7;
        for (int c = 0; c < 4; c++) {
            __syncthreads();
            for (int t = tid; t < 64 * 32; t += NTHR) {
                int rq = t & 31, k = t >> 5;
                *(float4*)&stg[k * BM + rq * 4] =
                    *(const float4*)&xb[(size_t)(c * 64 + k) * 1024 + s0 + rq * 4];
            }
            __syncthreads();
            if (tid < BM) {
                #pragma unroll 8
                for (int k = 0; k < 64; k++) { float v = stg[k * BM + tid]; xacc = fmaf(v, v, xacc); }
            }
            #pragma unroll
            for (int j = 0; j < 8; j++) {
                int k2l = cq * 8 + j;                  // 0..31 within chunk
                float v0 = stg[(k2l * 2) * BM + cpx];
                float v1 = stg[(k2l * 2 + 1) * BM + cpx];
                Ap[(c * 32 + k2l) * APAD + cpx] = pack_h2(v0, v1);
            }
        }
        __syncthreads();
        if (tid < BM) s_xs[tid] = xacc;
        __syncthreads();
    }

    // ---- HMMA mainloop: 8 n-iters, full B tile resident, warp tile 32x32 ----
    float tv1[4], tv2[4], tv3[4];
    int   ti1[4], ti2[4];
    #pragma unroll
    for (int e = 0; e < 4; e++) { tv1[e] = tv2[e] = tv3[e] = FLTMAX; ti1[e] = ti2[e] = 0x7fffffff; }

    const int lrow = tid >> 5, lseg = lane;     // B load role: 16 rows/pass, int4 seg

    for (int n0 = 0; n0 < NCODES; n0 += BN) {
        float acc[2][4][4];
        #pragma unroll
        for (int mb = 0; mb < 2; mb++)
            #pragma unroll
            for (int nb = 0; nb < 4; nb++)
                #pragma unroll
                for (int e = 0; e < 4; e++) acc[mb][nb][e] = 0.0f;

        __syncthreads();   // previous n-iter's reads of Bsm done
        #pragma unroll
        for (int i = 0; i < 8; i++) {
            int row = lrow + 16 * i;
            int4 v = *(const int4*)&g_wp[(size_t)row * NCODES + n0 + lseg * 4];
            *(int4*)&Bsm[row * APAD + lseg * 4] = v;
        }
        __syncthreads();

        #pragma unroll 4
        for (int ws = 0; ws < 16; ws++) {
            const int r0 = ws * 8 + tig, r1 = r0 + 4;
            uint32_t b0[4], b1[4];
            #pragma unroll
            for (int nb = 0; nb < 4; nb++) {
                int ncol = wn * 32 + nb * 8 + g;
                b0[nb] = Bsm[r0 * APAD + ncol];
                b1[nb] = Bsm[r1 * APAD + ncol];
            }
            #pragma unroll
            for (int mb = 0; mb < 2; mb++) {
                int m0 = wm * 32 + mb * 16;
                uint32_t a0 = Ap[r0 * APAD + m0 + g];
                uint32_t a1 = Ap[r0 * APAD + m0 + g + 8];
                uint32_t a2 = Ap[r1 * APAD + m0 + g];
                uint32_t a3 = Ap[r1 * APAD + m0 + g + 8];
                #pragma unroll
                for (int nb = 0; nb < 4; nb++)
                    mma16816(acc[mb][nb], a0, a1, a2, a3, b0[nb], b1[nb]);
            }
        }

        // ---- scoring with top-3 tracking: d2 = fl(fl(xs - fl(2*dot)) + wsq) ----
        #pragma unroll
        for (int nb = 0; nb < 4; nb++) {
            const int code0 = n0 + wn * 32 + nb * 8 + 2 * tig;
            const float wq0 = s_wsq[code0], wq1 = s_wsq[code0 + 1];
            #pragma unroll
            for (int mb = 0; mb < 2; mb++) {
                const float xs0 = s_xs[wm * 32 + mb * 16 + g];
                const float xs1 = s_xs[wm * 32 + mb * 16 + g + 8];
                #pragma unroll
                for (int q = 0; q < 4; q++) {
                    const float xsv = (q < 2) ? xs0 : xs1;
                    const float wqv = (q & 1) ? wq1 : wq0;
                    const int   cd  = code0 + (q & 1);
                    const int   e   = mb * 2 + (q >> 1);
                    float d = __fadd_rn(__fadd_rn(xsv, -__fmul_rn(2.0f, acc[mb][nb][q])), wqv);
                    if (d < tv1[e]) { tv3[e] = tv2[e]; tv2[e] = tv1[e]; ti2[e] = ti1[e]; tv1[e] = d; ti1[e] = cd; }
                    else if (d < tv2[e]) { tv3[e] = tv2[e]; tv2[e] = d; ti2[e] = cd; }
                    else if (d < tv3[e]) { tv3[e] = d; }
                }
            }
        }
    }

    // ---- dump slots, exact global top candidates, rescue flags (as in R8) ----
    __syncthreads();
    float* sv1 = (float*)smw;
    int*   si1 = (int*)(smw + 2048);
    float* sv2 = (float*)(smw + 4096);
    int*   si2 = (int*)(smw + 6144);
    float* sv3 = (float*)(smw + 8192);
    float* rv  = (float*)(smw + 10240);
    int*   ri  = (int*)(smw + 10752);
    #pragma unroll
    for (int e = 0; e < 4; e++) {
        int px = wm * 32 + (e >> 1) * 16 + g + 8 * (e & 1);
        int sl = wn * 4 + tig;
        sv1[px * 16 + sl] = tv1[e]; si1[px * 16 + sl] = ti1[e];
        sv2[px * 16 + sl] = tv2[e]; si2[px * 16 + sl] = ti2[e];
        sv3[px * 16 + sl] = tv3[e];
    }
    if (tid == 0) s_nflag = 0;
    __syncthreads();

    if (tid < BM) {
        float m1 = FLTMAX; int mi1 = 0x7fffffff;
        #pragma unroll
        for (int s = 0; s < 16; s++) {
            float v = sv1[tid * 16 + s]; int i = si1[tid * 16 + s];
            if (v < m1 || (v == m1 && i < mi1)) { m1 = v; mi1 = i; }
        }
        const float lim = m1 + MARGIN;
        int cnt = 1; bool full = false;
        s_cand[tid][0] = mi1;
        #pragma unroll
        for (int s = 0; s < 16; s++) {
            float v1 = sv1[tid * 16 + s], v2 = sv2[tid * 16 + s], v3 = sv3[tid * 16 + s];
            int   i1 = si1[tid * 16 + s], i2 = si2[tid * 16 + s];
            if (v1 <= lim && i1 != mi1) { if (cnt < 8) s_cand[tid][cnt] = i1; cnt++; }
            if (v2 <= lim && i2 != mi1) { if (cnt < 8) s_cand[tid][cnt] = i2; cnt++; }
            if (v3 <= lim) full = true;
        }
        if (cnt > 8) full = true;
        s_ccnt[tid] = full ? 255 : cnt;
        s_idx[tid] = mi1;
        if (full || cnt > 1) { int sl = atomicAdd(&s_nflag, 1); s_flag[sl] = tid; }
    }
    __syncthreads();

    // ---- rescue: exact sequential-fmaf rescoring (reference-decision-exact) ----
    const int nflag = s_nflag;
    for (int f = 0; f < nflag; f++) {
        const int px = s_flag[f];
        if (tid < 256) s_xrow[tid] = xb[(size_t)tid * 1024 + s0 + px];
        __syncthreads();
        const int cnt = s_ccnt[px];
        if (cnt != 255) {
            if (tid < cnt) {
                int code = s_cand[px][tid];
                const float* wr = w + (size_t)code * K_DIM;
                float dot = 0.0f;
                #pragma unroll 8
                for (int k = 0; k < K_DIM; k++) dot = fmaf(s_xrow[k], wr[k], dot);
                rv[tid] = __fadd_rn(__fadd_rn(s_xs[px], -__fmul_rn(2.0f, dot)), s_wsq[code]);
                ri[tid] = code;
            }
            __syncthreads();
            if (tid == 0) {
                float bv = FLTMAX; int bi = 0x7fffffff;
                for (int t = 0; t < cnt; t++) {
                    float v = rv[t]; int id = ri[t];
                    if (v < bv || (v == bv && id < bi)) { bv = v; bi = id; }
                }
                s_idx[px] = bi;
            }
        } else {
            float bv = FLTMAX; int bi = 0x7fffffff;
            #pragma unroll
            for (int j = 0; j < 2; j++) {
                int code = tid * 2 + j;
                const float* wr = w + (size_t)code * K_DIM;
                float dot = 0.0f;
                for (int k = 0; k < K_DIM; k++) dot = fmaf(s_xrow[k], wr[k], dot);
                float d2 = __fadd_rn(__fadd_rn(s_xs[px], -__fmul_rn(2.0f, dot)), s_wsq[code]);
                if (d2 < bv || (d2 == bv && code < bi)) { bv = d2; bi = code; }
            }
            rv[tid] = bv; ri[tid] = bi;
            __syncthreads();
            if (tid == 0) {
                float bvv = FLTMAX; int bii = 0x7fffffff;
                for (int t = 0; t < NTHR; t++) {
                    float v = rv[t]; int id = ri[t];
                    if (v < bvv || (v == bvv && id < bii)) { bvv = v; bii = id; }
                }
                s_idx[px] = bii;
            }
        }
        __syncthreads();
    }

    // ---- outputs ----
    if (tid < BM) out[2 * NQ + p0 + tid] = (float)s_idx[tid];

    const size_t obase = (size_t)b * (K_DIM * 1024) + s0;
    for (int t = tid; t < K_DIM * BM; t += NTHR) {
        int rp = t & 127, c = t >> 7;
        float q  = w[(size_t)s_idx[rp] * K_DIM + c];
        float xv = xb[(size_t)c * 1024 + s0 + rp];
        size_t o = obase + (size_t)c * 1024 + rp;
        out[o]      = q;
        out[NQ + o] = __fadd_rn(__fsub_rn(q, xv), xv);
    }
}

// ---------------------------------------------------------------------------
extern "C" void kernel_launch(void* const* d_in, const int* in_sizes, int n_in,
                              void* d_out, int out_size) {
    const float* x = (const float*)d_in[0];
    const float* w = (const float*)d_in[1];
    if (n_in >= 2 && in_sizes[0] == NCODES * K_DIM) {
        w = (const float*)d_in[0];
        x = (const float*)d_in[1];
    }
    float* out = (float*)d_out;

    const size_t smem = (size_t)(2 * 128 * APAD) * sizeof(uint32_t);  // 139264 B
    cudaFuncSetAttribute(vq_kernel, cudaFuncAttributeMaxDynamicSharedMemorySize, (int)smem);

    wsq_kernel<<<NCODES / 32, 256>>>(w);
    wpack_kernel<<<(NCODES * 128) / 256, 256>>>(w);
    vq_kernel<<<NPIX / BM, NTHR, smem>>>(x, w, out);
}

// round 15
// speedup vs baseline: 2.5884x; 1.8295x over previous
#include <cuda_runtime.h>
#include <cuda_fp16.h>
#include <cstdint>

#define K_DIM   256
#define NCODES  1024
#define NPIX    65536
#define NQ      16777216ull
#define BM      128           // pixels per CTA
#define BN      128           // codes per n-iter
#define NTHR    512
#define APAD    136           // pitch (b32 words): bank = (8*k2 + col) % 32, conflict-free
#define MARGIN  8e-4f         // > 2 * deterministic d2 error bound for fp16 products
#define FLTMAX  3.402823466e38f

__device__ float g_wsq[NCODES];
// Pair-packed fp16 codebook, [k2][code] layout (k2 = 0..127)
__device__ uint32_t g_wp[128 * NCODES];

static __device__ __forceinline__ uint32_t pack_h2(float a, float b) {
    __half2 h = __floats2half2_rn(a, b);
    return *(uint32_t*)&h;
}

__device__ __forceinline__ void mma16816(float* c, uint32_t a0, uint32_t a1, uint32_t a2, uint32_t a3,
                                         uint32_t b0, uint32_t b1) {
    asm volatile("mma.sync.aligned.m16n8k16.row.col.f32.f16.f16.f32 "
                 "{%0,%1,%2,%3}, {%4,%5,%6,%7}, {%8,%9}, {%0,%1,%2,%3};"
                 : "+f"(c[0]), "+f"(c[1]), "+f"(c[2]), "+f"(c[3])
                 : "r"(a0), "r"(a1), "r"(a2), "r"(a3), "r"(b0), "r"(b1));
}

// ---------------- merged prep kernel: wsq + fp16 pack (32 codes / block) ----------------
// PPITCH must keep row stride 16B-aligned for float4/float2 access: 264*4 = 1056 = 66*16.
#define PPITCH 264
__global__ void prep_kernel(const float* __restrict__ w) {
    __shared__ float s[32 * PPITCH];       // 33792 B
    const int blk = blockIdx.x, tid = threadIdx.x;
    const float* src = w + (size_t)blk * 32 * K_DIM;
    for (int i = tid; i < 32 * K_DIM / 4; i += 256) {
        int row = i >> 6, q = i & 63;
        *(float4*)&s[row * PPITCH + q * 4] = *(const float4*)&src[row * K_DIM + q * 4];
    }
    __syncthreads();
    if (tid < 32) {
        float acc = 0.0f;
        #pragma unroll 8
        for (int c = 0; c < K_DIM; c++) { float v = s[tid * PPITCH + c]; acc = fmaf(v, v, acc); }
        g_wsq[blk * 32 + tid] = acc;
    }
    // pack: coalesced writes (lanes sweep code)
    for (int t = tid; t < 32 * 128; t += 256) {
        int code = t & 31, k2 = t >> 5;
        float2 v = *(const float2*)&s[code * PPITCH + k2 * 2];
        g_wp[(size_t)k2 * NCODES + blk * 32 + code] = pack_h2(v.x, v.y);
    }
}

// ---------------- main kernel ----------------
__global__ __launch_bounds__(NTHR) void vq_kernel(
    const float* __restrict__ x,
    const float* __restrict__ w,
    float* __restrict__ out)
{
    extern __shared__ __align__(16) uint32_t smw[];
    uint32_t* Ap  = smw;                   // [128][APAD] fp16-pair-packed x
    uint32_t* Bsm = smw + 128 * APAD;      // [128][APAD] fp16-pair-packed codes; staging overlay
    __shared__ float s_wsq[NCODES];
    __shared__ float s_xs[BM];
    __shared__ int   s_idx[BM];
    __shared__ float s_xrow[K_DIM];
    __shared__ int   s_cand[BM][8];
    __shared__ int   s_ccnt[BM];
    __shared__ int   s_flag[BM];
    __shared__ int   s_nflag;

    const int tid  = threadIdx.x;
    const int wid  = tid >> 5, lane = tid & 31;
    const int g    = lane >> 2, tig = lane & 3;
    const int wm   = wid >> 2, wn = wid & 3;
    const int p0   = blockIdx.x * BM;
    const int b    = p0 >> 10;
    const int s0   = p0 & 1023;
    const float* xb = x + (size_t)b * (K_DIM * 1024);

    for (int t = tid; t < NCODES; t += NTHR) s_wsq[t] = g_wsq[t];

    // ---- stage x -> exact ||x||^2 + fp16-pair-packed Ap ----
    {
        float* stg = (float*)Bsm;          // [64 k][128 px] f32 chunk (32KB)
        float xacc = 0.0f;
        const int cpx = tid & 127, cq = tid >> 7;
        for (int c = 0; c < 4; c++) {
            __syncthreads();
            for (int t = tid; t < 64 * 32; t += NTHR) {
                int rq = t & 31, k = t >> 5;
                *(float4*)&stg[k * BM + rq * 4] =
                    *(const float4*)&xb[(size_t)(c * 64 + k) * 1024 + s0 + rq * 4];
            }
            __syncthreads();
            if (tid < BM) {
                #pragma unroll 8
                for (int k = 0; k < 64; k++) { float v = stg[k * BM + tid]; xacc = fmaf(v, v, xacc); }
            }
            #pragma unroll
            for (int j = 0; j < 8; j++) {
                int k2l = cq * 8 + j;
                float v0 = stg[(k2l * 2) * BM + cpx];
                float v1 = stg[(k2l * 2 + 1) * BM + cpx];
                Ap[(c * 32 + k2l) * APAD + cpx] = pack_h2(v0, v1);
            }
        }
        __syncthreads();
        if (tid < BM) s_xs[tid] = xacc;
        __syncthreads();
    }

    // ---- HMMA mainloop: 8 n-iters, full B tile resident, warp tile 32x32 ----
    float tv1[4], tv2[4], tv3[4];
    int   ti1[4], ti2[4];
    #pragma unroll
    for (int e = 0; e < 4; e++) { tv1[e] = tv2[e] = tv3[e] = FLTMAX; ti1[e] = ti2[e] = 0x7fffffff; }

    const int lrow = tid >> 5, lseg = lane;

    for (int n0 = 0; n0 < NCODES; n0 += BN) {
        float acc[2][4][4];
        #pragma unroll
        for (int mb = 0; mb < 2; mb++)
            #pragma unroll
            for (int nb = 0; nb < 4; nb++)
                #pragma unroll
                for (int e = 0; e < 4; e++) acc[mb][nb][e] = 0.0f;

        __syncthreads();
        #pragma unroll
        for (int i = 0; i < 8; i++) {
            int row = lrow + 16 * i;
            int4 v = *(const int4*)&g_wp[(size_t)row * NCODES + n0 + lseg * 4];
            *(int4*)&Bsm[row * APAD + lseg * 4] = v;
        }
        __syncthreads();

        #pragma unroll 4
        for (int ws = 0; ws < 16; ws++) {
            const int r0 = ws * 8 + tig, r1 = r0 + 4;
            uint32_t b0[4], b1[4];
            #pragma unroll
            for (int nb = 0; nb < 4; nb++) {
                int ncol = wn * 32 + nb * 8 + g;
                b0[nb] = Bsm[r0 * APAD + ncol];
                b1[nb] = Bsm[r1 * APAD + ncol];
            }
            #pragma unroll
            for (int mb = 0; mb < 2; mb++) {
                int m0 = wm * 32 + mb * 16;
                uint32_t a0 = Ap[r0 * APAD + m0 + g];
                uint32_t a1 = Ap[r0 * APAD + m0 + g + 8];
                uint32_t a2 = Ap[r1 * APAD + m0 + g];
                uint32_t a3 = Ap[r1 * APAD + m0 + g + 8];
                #pragma unroll
                for (int nb = 0; nb < 4; nb++)
                    mma16816(acc[mb][nb], a0, a1, a2, a3, b0[nb], b1[nb]);
            }
        }

        // ---- scoring with top-3 tracking: d2 = fl(fl(xs - fl(2*dot)) + wsq) ----
        #pragma unroll
        for (int nb = 0; nb < 4; nb++) {
            const int code0 = n0 + wn * 32 + nb * 8 + 2 * tig;
            const float wq0 = s_wsq[code0], wq1 = s_wsq[code0 + 1];
            #pragma unroll
            for (int mb = 0; mb < 2; mb++) {
                const float xs0 = s_xs[wm * 32 + mb * 16 + g];
                const float xs1 = s_xs[wm * 32 + mb * 16 + g + 8];
                #pragma unroll
                for (int q = 0; q < 4; q++) {
                    const float xsv = (q < 2) ? xs0 : xs1;
                    const float wqv = (q & 1) ? wq1 : wq0;
                    const int   cd  = code0 + (q & 1);
                    const int   e   = mb * 2 + (q >> 1);
                    float d = __fadd_rn(__fadd_rn(xsv, -__fmul_rn(2.0f, acc[mb][nb][q])), wqv);
                    if (d < tv1[e]) { tv3[e] = tv2[e]; tv2[e] = tv1[e]; ti2[e] = ti1[e]; tv1[e] = d; ti1[e] = cd; }
                    else if (d < tv2[e]) { tv3[e] = tv2[e]; tv2[e] = d; ti2[e] = cd; }
                    else if (d < tv3[e]) { tv3[e] = d; }
                }
            }
        }
    }

    // ---- dump slots, exact global winner + candidate collection ----
    __syncthreads();
    float* sv1 = (float*)smw;
    int*   si1 = (int*)(smw + 2048);
    float* sv2 = (float*)(smw + 4096);
    int*   si2 = (int*)(smw + 6144);
    float* sv3 = (float*)(smw + 8192);
    float* rv  = (float*)(smw + 10240);
    int*   ri  = (int*)(smw + 10752);
    #pragma unroll
    for (int e = 0; e < 4; e++) {
        int px = wm * 32 + (e >> 1) * 16 + g + 8 * (e & 1);
        int sl = wn * 4 + tig;
        sv1[px * 16 + sl] = tv1[e]; si1[px * 16 + sl] = ti1[e];
        sv2[px * 16 + sl] = tv2[e]; si2[px * 16 + sl] = ti2[e];
        sv3[px * 16 + sl] = tv3[e];
    }
    if (tid == 0) s_nflag = 0;
    __syncthreads();

    if (tid < BM) {
        float m1 = FLTMAX; int mi1 = 0x7fffffff;
        #pragma unroll
        for (int s = 0; s < 16; s++) {
            float v = sv1[tid * 16 + s]; int i = si1[tid * 16 + s];
            if (v < m1 || (v == m1 && i < mi1)) { m1 = v; mi1 = i; }
        }
        const float lim = m1 + MARGIN;
        int cnt = 1; bool full = false;
        s_cand[tid][0] = mi1;
        #pragma unroll
        for (int s = 0; s < 16; s++) {
            float v1 = sv1[tid * 16 + s], v2 = sv2[tid * 16 + s], v3 = sv3[tid * 16 + s];
            int   i1 = si1[tid * 16 + s], i2 = si2[tid * 16 + s];
            if (v1 <= lim && i1 != mi1) { if (cnt < 8) s_cand[tid][cnt] = i1; cnt++; }
            if (v2 <= lim && i2 != mi1) { if (cnt < 8) s_cand[tid][cnt] = i2; cnt++; }
            if (v3 <= lim) full = true;
        }
        if (cnt > 8) full = true;
        s_ccnt[tid] = full ? 255 : cnt;
        s_idx[tid] = mi1;
        if (full || cnt > 1) { int sl = atomicAdd(&s_nflag, 1); s_flag[sl] = tid; }
    }
    __syncthreads();

    // ---- rescue phase A: warp-parallel exact rescoring (lane = candidate) ----
    const int nflag = s_nflag;
    for (int f = wid; f < nflag; f += 16) {
        const int px  = s_flag[f];
        const int cnt = s_ccnt[px];
        if (cnt == 255) continue;
        float v = FLTMAX; int ci = 0x7fffffff;
        if (lane < cnt) {
            int code = s_cand[px][lane];
            const float* wr = w + (size_t)code * K_DIM;
            const float* xr = xb + s0 + px;
            float dot = 0.0f;
            #pragma unroll 8
            for (int k = 0; k < K_DIM; k++) dot = fmaf(xr[(size_t)k * 1024], wr[k], dot);
            v = __fadd_rn(__fadd_rn(s_xs[px], -__fmul_rn(2.0f, dot)), s_wsq[code]);
            ci = code;
        }
        #pragma unroll
        for (int off = 16; off; off >>= 1) {
            float ov = __shfl_xor_sync(0xffffffffu, v, off);
            int   oi = __shfl_xor_sync(0xffffffffu, ci, off);
            if (ov < v || (ov == v && oi < ci)) { v = ov; ci = oi; }
        }
        if (lane == 0) s_idx[px] = ci;
    }
    __syncthreads();

    // ---- rescue phase B: full 1024-code exact rescore (rare safety net) ----
    for (int f = 0; f < nflag; f++) {
        const int px = s_flag[f];
        if (s_ccnt[px] != 255) continue;
        if (tid < 256) s_xrow[tid] = xb[(size_t)tid * 1024 + s0 + px];
        __syncthreads();
        float bv = FLTMAX; int bi = 0x7fffffff;
        #pragma unroll
        for (int j = 0; j < 2; j++) {
            int code = tid * 2 + j;
            const float* wr = w + (size_t)code * K_DIM;
            float dot = 0.0f;
            for (int k = 0; k < K_DIM; k++) dot = fmaf(s_xrow[k], wr[k], dot);
            float d2 = __fadd_rn(__fadd_rn(s_xs[px], -__fmul_rn(2.0f, dot)), s_wsq[code]);
            if (d2 < bv || (d2 == bv && code < bi)) { bv = d2; bi = code; }
        }
        rv[tid] = bv; ri[tid] = bi;
        __syncthreads();
        if (tid == 0) {
            float bvv = FLTMAX; int bii = 0x7fffffff;
            for (int t = 0; t < NTHR; t++) {
                float v = rv[t]; int id = ri[t];
                if (v < bvv || (v == bvv && id < bii)) { bvv = v; bii = id; }
            }
            s_idx[px] = bii;
        }
        __syncthreads();
    }

    // ---- outputs ----
    if (tid < BM) out[2 * NQ + p0 + tid] = (float)s_idx[tid];

    const size_t obase = (size_t)b * (K_DIM * 1024) + s0;
    for (int t = tid; t < K_DIM * BM; t += NTHR) {
        int rp = t & 127, c = t >> 7;
        float q  = w[(size_t)s_idx[rp] * K_DIM + c];
        float xv = xb[(size_t)c * 1024 + s0 + rp];
        size_t o = obase + (size_t)c * 1024 + rp;
        out[o]      = q;
        out[NQ + o] = __fadd_rn(__fsub_rn(q, xv), xv);
    }
}

// ---------------------------------------------------------------------------
extern "C" void kernel_launch(void* const* d_in, const int* in_sizes, int n_in,
                              void* d_out, int out_size) {
    const float* x = (const float*)d_in[0];
    const float* w = (const float*)d_in[1];
    if (n_in >= 2 && in_sizes[0] == NCODES * K_DIM) {
        w = (const float*)d_in[0];
        x = (const float*)d_in[1];
    }
    float* out = (float*)d_out;

    const size_t smem = (size_t)(2 * 128 * APAD) * sizeof(uint32_t);  // 139264 B
    cudaFuncSetAttribute(vq_kernel, cudaFuncAttributeMaxDynamicSharedMemorySize, (int)smem);

    prep_kernel<<<NCODES / 32, 256>>>(w);
    vq_kernel<<<NPIX / BM, NTHR, smem>>>(x, w, out);
}